// round 9
// baseline (speedup 1.0000x reference)
#include <cuda_runtime.h>

#define EPSF 1e-3f

#define Bn 32
#define Hn 56
#define Wn 56
#define Cn 256
#define CMn 128
#define Mn (Bn*Hn*Wn)   // 100352 spatial positions

// Scratch (allocation-free rule: __device__ globals)
__device__ float g_h1[(size_t)Mn * CMn];   // after conv1+BN+relu
__device__ float g_h2[(size_t)Mn * CMn];   // after grouped conv2+BN+relu

// ---------------------------------------------------------------------------
// Kernel 1: 1x1 conv 256->128 (+bias, BN, relu).  GEMM: C[M,128] = A[M,256]*B[256,128]
// Tile 128x128, BK=16, 256 threads, 8x8 per-thread microtile.
// ---------------------------------------------------------------------------
__global__ __launch_bounds__(256, 2)
void k_conv1(const float* __restrict__ x, const float* __restrict__ w1,
             const float* __restrict__ b1, const float* __restrict__ g1,
             const float* __restrict__ be1, const float* __restrict__ m1,
             const float* __restrict__ v1)
{
    __shared__ float As[16][132];   // transposed A tile: As[k][m], padded
    __shared__ float Bs[16][132];   // Bs[k][n], padded

    const int tid = threadIdx.x;
    const int rowBase = blockIdx.x * 128;

    const int m0 = (tid >> 4) * 8;
    const int n0 = (tid & 15) * 8;
    const int am = tid >> 2;            // A-load row 0..63 (+64)
    const int ak = (tid & 3) * 4;       // A-load k offset {0,4,8,12}
    const int bk = tid >> 5;            // B-load row 0..7 (+8)
    const int bn = (tid & 31) * 4;      // B-load col*4

    float acc[8][8];
    #pragma unroll
    for (int i = 0; i < 8; i++)
        #pragma unroll
        for (int j = 0; j < 8; j++) acc[i][j] = 0.f;

    for (int kt = 0; kt < 256; kt += 16) {
        #pragma unroll
        for (int h = 0; h < 2; h++) {
            int m = am + h * 64;
            float4 v = *(const float4*)(x + (size_t)(rowBase + m) * 256 + kt + ak);
            As[ak+0][m] = v.x; As[ak+1][m] = v.y;
            As[ak+2][m] = v.z; As[ak+3][m] = v.w;
        }
        #pragma unroll
        for (int h = 0; h < 2; h++) {
            int k = bk + h * 8;
            *(float4*)&Bs[k][bn] = *(const float4*)(w1 + (size_t)(kt + k) * 128 + bn);
        }
        __syncthreads();
        #pragma unroll
        for (int k = 0; k < 16; k++) {
            float a[8], b[8];
            *(float4*)&a[0] = *(float4*)&As[k][m0];
            *(float4*)&a[4] = *(float4*)&As[k][m0+4];
            *(float4*)&b[0] = *(float4*)&Bs[k][n0];
            *(float4*)&b[4] = *(float4*)&Bs[k][n0+4];
            #pragma unroll
            for (int i = 0; i < 8; i++)
                #pragma unroll
                for (int j = 0; j < 8; j++)
                    acc[i][j] = fmaf(a[i], b[j], acc[i][j]);
        }
        __syncthreads();
    }

    // Epilogue: y = relu((conv+b1)*inv + be1 - m1*inv) = relu(conv*inv + (b1-m1)*inv + be1)
    float sc[8], sh[8];
    #pragma unroll
    for (int j = 0; j < 8; j++) {
        int n = n0 + j;
        float inv = g1[n] * rsqrtf(v1[n] + EPSF);
        sc[j] = inv;
        sh[j] = (b1[n] - m1[n]) * inv + be1[n];
    }
    #pragma unroll
    for (int i = 0; i < 8; i++) {
        size_t row = (size_t)(rowBase + m0 + i) * 128;
        #pragma unroll
        for (int j = 0; j < 8; j += 4) {
            float4 o;
            o.x = fmaxf(fmaf(acc[i][j+0], sc[j+0], sh[j+0]), 0.f);
            o.y = fmaxf(fmaf(acc[i][j+1], sc[j+1], sh[j+1]), 0.f);
            o.z = fmaxf(fmaf(acc[i][j+2], sc[j+2], sh[j+2]), 0.f);
            o.w = fmaxf(fmaf(acc[i][j+3], sc[j+3], sh[j+3]), 0.f);
            *(float4*)(g_h1 + row + n0 + j) = o;
        }
    }
}

// ---------------------------------------------------------------------------
// Kernel 2: grouped 3x3 conv (32 groups of 4->4) + bias + BN + relu.
// Block = (y-row, batch, 32-channel chunk = 8 groups). 3 halo rows in smem.
// ---------------------------------------------------------------------------
__global__ __launch_bounds__(256)
void k_conv2(const float* __restrict__ w2, const float* __restrict__ b2,
             const float* __restrict__ g2, const float* __restrict__ be2,
             const float* __restrict__ m2, const float* __restrict__ v2)
{
    __shared__ float s_in[3][58][32];   // rows y-1..y+1, cols with halo, 32 ch
    __shared__ float s_w[9][4][32];     // [kh*3+kw][ci][co_local]
    __shared__ float s_sc[32], s_sh[32];

    const int tid = threadIdx.x;
    const int y   = blockIdx.x;         // 0..55
    const int b   = blockIdx.y;         // 0..31
    const int ch  = blockIdx.z;         // 0..3  (chunk of 32 channels)

    for (int idx = tid; idx < 3*58*32; idx += 256) {
        int r   = idx / (58*32);
        int rem = idx % (58*32);
        int xx  = rem / 32;
        int cc  = rem % 32;
        int yy  = y + r - 1;
        int xg  = xx - 1;
        float v = 0.f;
        if (yy >= 0 && yy < 56 && xg >= 0 && xg < 56)
            v = g_h1[(size_t)((b*56 + yy)*56 + xg) * 128 + ch*32 + cc];
        s_in[r][xx][cc] = v;
    }
    for (int idx = tid; idx < 9*4*32; idx += 256) {
        int kk  = idx / 128;
        int rem = idx % 128;
        int ci  = rem / 32;
        int co  = rem % 32;
        s_w[kk][ci][co] = w2[(size_t)(kk*4 + ci)*128 + ch*32 + co];
    }
    if (tid < 32) {
        int c = ch*32 + tid;
        float inv = g2[c] * rsqrtf(v2[c] + EPSF);
        s_sc[tid] = inv;
        s_sh[tid] = (b2[c] - m2[c]) * inv + be2[c];
    }
    __syncthreads();

    const int co  = tid & 31;            // local out channel
    const int cib = (co >> 2) * 4;       // local input-channel base of its group
    for (int xi = tid >> 5; xi < 56; xi += 8) {
        float acc = 0.f;
        #pragma unroll
        for (int kh = 0; kh < 3; kh++)
            #pragma unroll
            for (int kw = 0; kw < 3; kw++)
                #pragma unroll
                for (int ci = 0; ci < 4; ci++)
                    acc = fmaf(s_in[kh][xi+kw][cib+ci], s_w[kh*3+kw][ci][co], acc);
        float o = fmaxf(fmaf(acc, s_sc[co], s_sh[co]), 0.f);
        g_h2[(size_t)((b*56 + y)*56 + xi) * 128 + ch*32 + co] = o;
    }
}

// ---------------------------------------------------------------------------
// Kernel 3: 1x1 conv 128->256 + b3 + residual(x) + relu.
// GEMM: C[M,256] = A[M,128]*B[128,256]; grid.y = N-chunk of 128.
// ---------------------------------------------------------------------------
__global__ __launch_bounds__(256, 2)
void k_conv3(const float* __restrict__ x, const float* __restrict__ w3,
             const float* __restrict__ b3, float* __restrict__ out)
{
    __shared__ float As[16][132];
    __shared__ float Bs[16][132];

    const int tid = threadIdx.x;
    const int rowBase = blockIdx.x * 128;
    const int nBase   = blockIdx.y * 128;

    const int m0 = (tid >> 4) * 8;
    const int n0 = (tid & 15) * 8;
    const int am = tid >> 2;
    const int ak = (tid & 3) * 4;
    const int bk = tid >> 5;
    const int bn = (tid & 31) * 4;

    float acc[8][8];
    #pragma unroll
    for (int i = 0; i < 8; i++)
        #pragma unroll
        for (int j = 0; j < 8; j++) acc[i][j] = 0.f;

    for (int kt = 0; kt < 128; kt += 16) {
        #pragma unroll
        for (int h = 0; h < 2; h++) {
            int m = am + h * 64;
            float4 v = *(const float4*)(g_h2 + (size_t)(rowBase + m) * 128 + kt + ak);
            As[ak+0][m] = v.x; As[ak+1][m] = v.y;
            As[ak+2][m] = v.z; As[ak+3][m] = v.w;
        }
        #pragma unroll
        for (int h = 0; h < 2; h++) {
            int k = bk + h * 8;
            *(float4*)&Bs[k][bn] = *(const float4*)(w3 + (size_t)(kt + k) * 256 + nBase + bn);
        }
        __syncthreads();
        #pragma unroll
        for (int k = 0; k < 16; k++) {
            float a[8], b[8];
            *(float4*)&a[0] = *(float4*)&As[k][m0];
            *(float4*)&a[4] = *(float4*)&As[k][m0+4];
            *(float4*)&b[0] = *(float4*)&Bs[k][n0];
            *(float4*)&b[4] = *(float4*)&Bs[k][n0+4];
            #pragma unroll
            for (int i = 0; i < 8; i++)
                #pragma unroll
                for (int j = 0; j < 8; j++)
                    acc[i][j] = fmaf(a[i], b[j], acc[i][j]);
        }
        __syncthreads();
    }

    float bv[8];
    #pragma unroll
    for (int j = 0; j < 8; j++) bv[j] = b3[nBase + n0 + j];

    #pragma unroll
    for (int i = 0; i < 8; i++) {
        int m = rowBase + m0 + i;
        #pragma unroll
        for (int j = 0; j < 8; j += 4) {
            size_t off = (size_t)m * 256 + nBase + n0 + j;
            float4 xr = *(const float4*)(x + off);
            float4 o;
            o.x = fmaxf(acc[i][j+0] + bv[j+0] + xr.x, 0.f);
            o.y = fmaxf(acc[i][j+1] + bv[j+1] + xr.y, 0.f);
            o.z = fmaxf(acc[i][j+2] + bv[j+2] + xr.z, 0.f);
            o.w = fmaxf(acc[i][j+3] + bv[j+3] + xr.w, 0.f);
            *(float4*)(out + off) = o;
        }
    }
}

// ---------------------------------------------------------------------------
extern "C" void kernel_launch(void* const* d_in, const int* in_sizes, int n_in,
                              void* d_out, int out_size)
{
    const float* x   = (const float*)d_in[0];
    const float* w1  = (const float*)d_in[1];
    const float* b1  = (const float*)d_in[2];
    const float* g1  = (const float*)d_in[3];
    const float* be1 = (const float*)d_in[4];
    const float* m1  = (const float*)d_in[5];
    const float* v1  = (const float*)d_in[6];
    const float* w2  = (const float*)d_in[7];
    const float* b2  = (const float*)d_in[8];
    const float* g2  = (const float*)d_in[9];
    const float* be2 = (const float*)d_in[10];
    const float* m2  = (const float*)d_in[11];
    const float* v2  = (const float*)d_in[12];
    const float* w3  = (const float*)d_in[13];
    const float* b3  = (const float*)d_in[14];
    float* out = (float*)d_out;

    k_conv1<<<Mn/128, 256>>>(x, w1, b1, g1, be1, m1, v1);
    k_conv2<<<dim3(56, 32, 4), 256>>>(w2, b2, g2, be2, m2, v2);
    k_conv3<<<dim3(Mn/128, 2), 256>>>(x, w3, b3, out);
}

// round 12
// speedup vs baseline: 1.0014x; 1.0014x over previous
#include <cuda_runtime.h>

#define EPSF 1e-3f

#define Bn 32
#define Hn 56
#define Wn 56
#define Cn 256
#define CMn 128
#define Mn (Bn*Hn*Wn)   // 100352 spatial positions

// Scratch (allocation-free rule: __device__ globals)
__device__ float g_h1[(size_t)Mn * CMn];   // after conv1+BN+relu
__device__ float g_h2[(size_t)Mn * CMn];   // after grouped conv2+BN+relu

// ---------------------------------------------------------------------------
// Kernel 1: 1x1 conv 256->128 (+bias, BN, relu).  GEMM: C[M,128] = A[M,256]*B[256,128]
// Tile 128x128, BK=16, 256 threads, 8x8 per-thread microtile.
// ---------------------------------------------------------------------------
__global__ __launch_bounds__(256, 2)
void k_conv1(const float* __restrict__ x, const float* __restrict__ w1,
             const float* __restrict__ b1, const float* __restrict__ g1,
             const float* __restrict__ be1, const float* __restrict__ m1,
             const float* __restrict__ v1)
{
    __shared__ float As[16][132];   // transposed A tile: As[k][m], padded
    __shared__ float Bs[16][132];   // Bs[k][n], padded

    const int tid = threadIdx.x;
    const int rowBase = blockIdx.x * 128;

    const int m0 = (tid >> 4) * 8;
    const int n0 = (tid & 15) * 8;
    const int am = tid >> 2;            // A-load row 0..63 (+64)
    const int ak = (tid & 3) * 4;       // A-load k offset {0,4,8,12}
    const int bk = tid >> 5;            // B-load row 0..7 (+8)
    const int bn = (tid & 31) * 4;      // B-load col*4

    float acc[8][8];
    #pragma unroll
    for (int i = 0; i < 8; i++)
        #pragma unroll
        for (int j = 0; j < 8; j++) acc[i][j] = 0.f;

    for (int kt = 0; kt < 256; kt += 16) {
        #pragma unroll
        for (int h = 0; h < 2; h++) {
            int m = am + h * 64;
            float4 v = *(const float4*)(x + (size_t)(rowBase + m) * 256 + kt + ak);
            As[ak+0][m] = v.x; As[ak+1][m] = v.y;
            As[ak+2][m] = v.z; As[ak+3][m] = v.w;
        }
        #pragma unroll
        for (int h = 0; h < 2; h++) {
            int k = bk + h * 8;
            *(float4*)&Bs[k][bn] = *(const float4*)(w1 + (size_t)(kt + k) * 128 + bn);
        }
        __syncthreads();
        #pragma unroll
        for (int k = 0; k < 16; k++) {
            float a[8], b[8];
            *(float4*)&a[0] = *(float4*)&As[k][m0];
            *(float4*)&a[4] = *(float4*)&As[k][m0+4];
            *(float4*)&b[0] = *(float4*)&Bs[k][n0];
            *(float4*)&b[4] = *(float4*)&Bs[k][n0+4];
            #pragma unroll
            for (int i = 0; i < 8; i++)
                #pragma unroll
                for (int j = 0; j < 8; j++)
                    acc[i][j] = fmaf(a[i], b[j], acc[i][j]);
        }
        __syncthreads();
    }

    // Epilogue: y = relu((conv+b1)*inv + be1 - m1*inv) = relu(conv*inv + (b1-m1)*inv + be1)
    float sc[8], sh[8];
    #pragma unroll
    for (int j = 0; j < 8; j++) {
        int n = n0 + j;
        float inv = g1[n] * rsqrtf(v1[n] + EPSF);
        sc[j] = inv;
        sh[j] = (b1[n] - m1[n]) * inv + be1[n];
    }
    #pragma unroll
    for (int i = 0; i < 8; i++) {
        size_t row = (size_t)(rowBase + m0 + i) * 128;
        #pragma unroll
        for (int j = 0; j < 8; j += 4) {
            float4 o;
            o.x = fmaxf(fmaf(acc[i][j+0], sc[j+0], sh[j+0]), 0.f);
            o.y = fmaxf(fmaf(acc[i][j+1], sc[j+1], sh[j+1]), 0.f);
            o.z = fmaxf(fmaf(acc[i][j+2], sc[j+2], sh[j+2]), 0.f);
            o.w = fmaxf(fmaf(acc[i][j+3], sc[j+3], sh[j+3]), 0.f);
            *(float4*)(g_h1 + row + n0 + j) = o;
        }
    }
}

// ---------------------------------------------------------------------------
// Kernel 2: grouped 3x3 conv (32 groups of 4->4) + bias + BN + relu.
// Block = (y-row, batch, 32-channel chunk = 8 groups). 3 halo rows in smem.
// ---------------------------------------------------------------------------
__global__ __launch_bounds__(256)
void k_conv2(const float* __restrict__ w2, const float* __restrict__ b2,
             const float* __restrict__ g2, const float* __restrict__ be2,
             const float* __restrict__ m2, const float* __restrict__ v2)
{
    __shared__ float s_in[3][58][32];   // rows y-1..y+1, cols with halo, 32 ch
    __shared__ float s_w[9][4][32];     // [kh*3+kw][ci][co_local]
    __shared__ float s_sc[32], s_sh[32];

    const int tid = threadIdx.x;
    const int y   = blockIdx.x;         // 0..55
    const int b   = blockIdx.y;         // 0..31
    const int ch  = blockIdx.z;         // 0..3  (chunk of 32 channels)

    for (int idx = tid; idx < 3*58*32; idx += 256) {
        int r   = idx / (58*32);
        int rem = idx % (58*32);
        int xx  = rem / 32;
        int cc  = rem % 32;
        int yy  = y + r - 1;
        int xg  = xx - 1;
        float v = 0.f;
        if (yy >= 0 && yy < 56 && xg >= 0 && xg < 56)
            v = g_h1[(size_t)((b*56 + yy)*56 + xg) * 128 + ch*32 + cc];
        s_in[r][xx][cc] = v;
    }
    for (int idx = tid; idx < 9*4*32; idx += 256) {
        int kk  = idx / 128;
        int rem = idx % 128;
        int ci  = rem / 32;
        int co  = rem % 32;
        s_w[kk][ci][co] = w2[(size_t)(kk*4 + ci)*128 + ch*32 + co];
    }
    if (tid < 32) {
        int c = ch*32 + tid;
        float inv = g2[c] * rsqrtf(v2[c] + EPSF);
        s_sc[tid] = inv;
        s_sh[tid] = (b2[c] - m2[c]) * inv + be2[c];
    }
    __syncthreads();

    const int co  = tid & 31;            // local out channel
    const int cib = (co >> 2) * 4;       // local input-channel base of its group
    for (int xi = tid >> 5; xi < 56; xi += 8) {
        float acc = 0.f;
        #pragma unroll
        for (int kh = 0; kh < 3; kh++)
            #pragma unroll
            for (int kw = 0; kw < 3; kw++)
                #pragma unroll
                for (int ci = 0; ci < 4; ci++)
                    acc = fmaf(s_in[kh][xi+kw][cib+ci], s_w[kh*3+kw][ci][co], acc);
        float o = fmaxf(fmaf(acc, s_sc[co], s_sh[co]), 0.f);
        g_h2[(size_t)((b*56 + y)*56 + xi) * 128 + ch*32 + co] = o;
    }
}

// ---------------------------------------------------------------------------
// Kernel 3: 1x1 conv 128->256 + b3 + residual(x) + relu.
// GEMM: C[M,256] = A[M,128]*B[128,256]; grid.y = N-chunk of 128.
// ---------------------------------------------------------------------------
__global__ __launch_bounds__(256, 2)
void k_conv3(const float* __restrict__ x, const float* __restrict__ w3,
             const float* __restrict__ b3, float* __restrict__ out)
{
    __shared__ float As[16][132];
    __shared__ float Bs[16][132];

    const int tid = threadIdx.x;
    const int rowBase = blockIdx.x * 128;
    const int nBase   = blockIdx.y * 128;

    const int m0 = (tid >> 4) * 8;
    const int n0 = (tid & 15) * 8;
    const int am = tid >> 2;
    const int ak = (tid & 3) * 4;
    const int bk = tid >> 5;
    const int bn = (tid & 31) * 4;

    float acc[8][8];
    #pragma unroll
    for (int i = 0; i < 8; i++)
        #pragma unroll
        for (int j = 0; j < 8; j++) acc[i][j] = 0.f;

    for (int kt = 0; kt < 128; kt += 16) {
        #pragma unroll
        for (int h = 0; h < 2; h++) {
            int m = am + h * 64;
            float4 v = *(const float4*)(g_h2 + (size_t)(rowBase + m) * 128 + kt + ak);
            As[ak+0][m] = v.x; As[ak+1][m] = v.y;
            As[ak+2][m] = v.z; As[ak+3][m] = v.w;
        }
        #pragma unroll
        for (int h = 0; h < 2; h++) {
            int k = bk + h * 8;
            *(float4*)&Bs[k][bn] = *(const float4*)(w3 + (size_t)(kt + k) * 256 + nBase + bn);
        }
        __syncthreads();
        #pragma unroll
        for (int k = 0; k < 16; k++) {
            float a[8], b[8];
            *(float4*)&a[0] = *(float4*)&As[k][m0];
            *(float4*)&a[4] = *(float4*)&As[k][m0+4];
            *(float4*)&b[0] = *(float4*)&Bs[k][n0];
            *(float4*)&b[4] = *(float4*)&Bs[k][n0+4];
            #pragma unroll
            for (int i = 0; i < 8; i++)
                #pragma unroll
                for (int j = 0; j < 8; j++)
                    acc[i][j] = fmaf(a[i], b[j], acc[i][j]);
        }
        __syncthreads();
    }

    float bv[8];
    #pragma unroll
    for (int j = 0; j < 8; j++) bv[j] = b3[nBase + n0 + j];

    #pragma unroll
    for (int i = 0; i < 8; i++) {
        int m = rowBase + m0 + i;
        #pragma unroll
        for (int j = 0; j < 8; j += 4) {
            size_t off = (size_t)m * 256 + nBase + n0 + j;
            float4 xr = *(const float4*)(x + off);
            float4 o;
            o.x = fmaxf(acc[i][j+0] + bv[j+0] + xr.x, 0.f);
            o.y = fmaxf(acc[i][j+1] + bv[j+1] + xr.y, 0.f);
            o.z = fmaxf(acc[i][j+2] + bv[j+2] + xr.z, 0.f);
            o.w = fmaxf(acc[i][j+3] + bv[j+3] + xr.w, 0.f);
            *(float4*)(out + off) = o;
        }
    }
}

// ---------------------------------------------------------------------------
extern "C" void kernel_launch(void* const* d_in, const int* in_sizes, int n_in,
                              void* d_out, int out_size)
{
    const float* x   = (const float*)d_in[0];
    const float* w1  = (const float*)d_in[1];
    const float* b1  = (const float*)d_in[2];
    const float* g1  = (const float*)d_in[3];
    const float* be1 = (const float*)d_in[4];
    const float* m1  = (const float*)d_in[5];
    const float* v1  = (const float*)d_in[6];
    const float* w2  = (const float*)d_in[7];
    const float* b2  = (const float*)d_in[8];
    const float* g2  = (const float*)d_in[9];
    const float* be2 = (const float*)d_in[10];
    const float* m2  = (const float*)d_in[11];
    const float* v2  = (const float*)d_in[12];
    const float* w3  = (const float*)d_in[13];
    const float* b3  = (const float*)d_in[14];
    float* out = (float*)d_out;

    k_conv1<<<Mn/128, 256>>>(x, w1, b1, g1, be1, m1, v1);
    k_conv2<<<dim3(56, 32, 4), 256>>>(w2, b2, g2, be2, m2, v2);
    k_conv3<<<dim3(Mn/128, 2), 256>>>(x, w3, b3, out);
}

// round 17
// speedup vs baseline: 1.6942x; 1.6918x over previous
#include <cuda_runtime.h>
#include <cstdint>

#define EPSF 1e-3f

#define Bn 32
#define Hn 56
#define Wn 56
#define Cn 256
#define CMn 128
#define Mn (Bn*Hn*Wn)   // 100352 spatial positions (784 * 128)

// Scratch (allocation-free rule: __device__ globals)
__device__ float g_h1[(size_t)Mn * CMn];   // after conv1+BN+relu
__device__ float g_h2[(size_t)Mn * CMn];   // after grouped conv2+BN+relu

// ---------------------------------------------------------------------------
// TF32 helpers
// ---------------------------------------------------------------------------
__device__ __forceinline__ uint32_t f2tf(float x) {
    uint32_t r;
    asm("cvt.rna.tf32.f32 %0, %1;" : "=r"(r) : "f"(x));
    return r;
}

__device__ __forceinline__ void mma_tf32(float c[4], const uint32_t a[4], const uint32_t b[2]) {
    asm volatile(
        "mma.sync.aligned.m16n8k8.row.col.f32.tf32.tf32.f32 "
        "{%0,%1,%2,%3}, {%4,%5,%6,%7}, {%8,%9}, {%0,%1,%2,%3};\n"
        : "+f"(c[0]), "+f"(c[1]), "+f"(c[2]), "+f"(c[3])
        : "r"(a[0]), "r"(a[1]), "r"(a[2]), "r"(a[3]),
          "r"(b[0]), "r"(b[1]));
}

// ---------------------------------------------------------------------------
// Kernel 1 (TF32 MMA): 1x1 conv 256->128 (+bias, BN, relu).
// GEMM: C[M,128] = A[M,256] * B[256,128].  Block tile 128x128, BK=16.
// 8 warps in 2(M)x4(N); warp tile 64x32; m16n8k8 frags 4x4 per warp.
// ---------------------------------------------------------------------------
__global__ __launch_bounds__(256, 2)
void k_conv1(const float* __restrict__ x, const float* __restrict__ w1,
             const float* __restrict__ b1, const float* __restrict__ g1,
             const float* __restrict__ be1, const float* __restrict__ m1,
             const float* __restrict__ v1)
{
    __shared__ uint32_t As[128][20];    // [m][k], pad 20 -> conflict-free frag loads
    __shared__ uint32_t Bs[16][136];    // [k][n], pad 136 (=8 mod 32) -> conflict-free

    const int tid  = threadIdx.x;
    const int lane = tid & 31;
    const int wid  = tid >> 5;
    const int wm   = (wid >> 2) * 64;   // warp M offset in tile
    const int wn   = (wid & 3) * 32;    // warp N offset in tile
    const int rowBase = blockIdx.x * 128;

    const int arow = tid >> 2;          // A-load row (0..63, +64)
    const int akc  = (tid & 3) * 4;     // A-load k base
    const int bk   = tid >> 5;          // B-load k row (0..7, +8)
    const int bn0  = (tid & 31) * 4;    // B-load n base

    const int lg = lane >> 2;           // groupID
    const int lt = lane & 3;            // thread in group

    float c[4][4][4];
    #pragma unroll
    for (int i = 0; i < 4; i++)
        #pragma unroll
        for (int j = 0; j < 4; j++)
            #pragma unroll
            for (int t = 0; t < 4; t++) c[i][j][t] = 0.f;

    for (int kt = 0; kt < 256; kt += 16) {
        #pragma unroll
        for (int h = 0; h < 2; h++) {
            int r = arow + h * 64;
            float4 v = *(const float4*)(x + (size_t)(rowBase + r) * 256 + kt + akc);
            uint4 s = { f2tf(v.x), f2tf(v.y), f2tf(v.z), f2tf(v.w) };
            *(uint4*)&As[r][akc] = s;
        }
        #pragma unroll
        for (int h = 0; h < 2; h++) {
            int k = bk + h * 8;
            float4 v = *(const float4*)(w1 + (size_t)(kt + k) * 128 + bn0);
            uint4 s = { f2tf(v.x), f2tf(v.y), f2tf(v.z), f2tf(v.w) };
            *(uint4*)&Bs[k][bn0] = s;
        }
        __syncthreads();

        #pragma unroll
        for (int ks = 0; ks < 16; ks += 8) {
            uint32_t a[4][4];
            #pragma unroll
            for (int mi = 0; mi < 4; mi++) {
                int r0 = wm + mi * 16 + lg;
                a[mi][0] = As[r0    ][ks + lt    ];
                a[mi][1] = As[r0 + 8][ks + lt    ];
                a[mi][2] = As[r0    ][ks + lt + 4];
                a[mi][3] = As[r0 + 8][ks + lt + 4];
            }
            uint32_t b[4][2];
            #pragma unroll
            for (int nj = 0; nj < 4; nj++) {
                int nn = wn + nj * 8 + lg;
                b[nj][0] = Bs[ks + lt    ][nn];
                b[nj][1] = Bs[ks + lt + 4][nn];
            }
            #pragma unroll
            for (int mi = 0; mi < 4; mi++)
                #pragma unroll
                for (int nj = 0; nj < 4; nj++)
                    mma_tf32(c[mi][nj], a[mi], b[nj]);
        }
        __syncthreads();
    }

    // Epilogue: relu(conv*inv + (b1-m1)*inv + be1)
    float sc[4][2], sh[4][2];
    #pragma unroll
    for (int nj = 0; nj < 4; nj++)
        #pragma unroll
        for (int t = 0; t < 2; t++) {
            int n = wn + nj * 8 + 2 * lt + t;
            float inv = g1[n] * rsqrtf(v1[n] + EPSF);
            sc[nj][t] = inv;
            sh[nj][t] = (b1[n] - m1[n]) * inv + be1[n];
        }
    #pragma unroll
    for (int mi = 0; mi < 4; mi++)
        #pragma unroll
        for (int h = 0; h < 2; h++) {
            size_t row = (size_t)(rowBase + wm + mi * 16 + lg + h * 8) * 128;
            #pragma unroll
            for (int nj = 0; nj < 4; nj++) {
                float2 o;
                o.x = fmaxf(fmaf(c[mi][nj][2*h+0], sc[nj][0], sh[nj][0]), 0.f);
                o.y = fmaxf(fmaf(c[mi][nj][2*h+1], sc[nj][1], sh[nj][1]), 0.f);
                *(float2*)(g_h1 + row + wn + nj * 8 + 2 * lt) = o;
            }
        }
}

// ---------------------------------------------------------------------------
// Kernel 2: grouped 3x3 conv (32 groups of 4->4) + bias + BN + relu.
// Weights in registers; input reads as float4 per group (9 LDS.128/output).
// ---------------------------------------------------------------------------
__global__ __launch_bounds__(256)
void k_conv2(const float* __restrict__ w2, const float* __restrict__ b2,
             const float* __restrict__ g2, const float* __restrict__ be2,
             const float* __restrict__ m2, const float* __restrict__ v2)
{
    __shared__ float s_in[3][58][32];   // rows y-1..y+1, cols with halo, 32 ch
    __shared__ float s_w[9][4][32];     // [kh*3+kw][ci][co_local]
    __shared__ float s_sc[32], s_sh[32];

    const int tid = threadIdx.x;
    const int y   = blockIdx.x;         // 0..55
    const int b   = blockIdx.y;         // 0..31
    const int ch  = blockIdx.z;         // 0..3  (chunk of 32 channels)

    for (int idx = tid; idx < 3*58*32; idx += 256) {
        int r   = idx / (58*32);
        int rem = idx % (58*32);
        int xx  = rem / 32;
        int cc  = rem % 32;
        int yy  = y + r - 1;
        int xg  = xx - 1;
        float v = 0.f;
        if (yy >= 0 && yy < 56 && xg >= 0 && xg < 56)
            v = g_h1[(size_t)((b*56 + yy)*56 + xg) * 128 + ch*32 + cc];
        s_in[r][xx][cc] = v;
    }
    for (int idx = tid; idx < 9*4*32; idx += 256) {
        int kk  = idx / 128;
        int rem = idx % 128;
        int ci  = rem / 32;
        int co  = rem % 32;
        s_w[kk][ci][co] = w2[(size_t)(kk*4 + ci)*128 + ch*32 + co];
    }
    if (tid < 32) {
        int cidx = ch*32 + tid;
        float inv = g2[cidx] * rsqrtf(v2[cidx] + EPSF);
        s_sc[tid] = inv;
        s_sh[tid] = (b2[cidx] - m2[cidx]) * inv + be2[cidx];
    }
    __syncthreads();

    const int co  = tid & 31;            // local out channel
    const int cib = (co >> 2) * 4;       // local input-channel base of its group

    float wr[9][4];
    #pragma unroll
    for (int kk = 0; kk < 9; kk++)
        #pragma unroll
        for (int ci = 0; ci < 4; ci++)
            wr[kk][ci] = s_w[kk][ci][co];

    const float scv = s_sc[co];
    const float shv = s_sh[co];

    for (int xi = tid >> 5; xi < 56; xi += 8) {
        float acc = 0.f;
        #pragma unroll
        for (int kh = 0; kh < 3; kh++)
            #pragma unroll
            for (int kw = 0; kw < 3; kw++) {
                float4 iv = *(const float4*)&s_in[kh][xi + kw][cib];
                acc = fmaf(iv.x, wr[kh*3+kw][0], acc);
                acc = fmaf(iv.y, wr[kh*3+kw][1], acc);
                acc = fmaf(iv.z, wr[kh*3+kw][2], acc);
                acc = fmaf(iv.w, wr[kh*3+kw][3], acc);
            }
        float o = fmaxf(fmaf(acc, scv, shv), 0.f);
        g_h2[(size_t)((b*56 + y)*56 + xi) * 128 + ch*32 + co] = o;
    }
}

// ---------------------------------------------------------------------------
// Kernel 3 (TF32 MMA): 1x1 conv 128->256 + b3 + residual(x) + relu.
// GEMM: C[M,256] = A[M,128]*B[128,256]; grid.y = N-chunk of 128.
// ---------------------------------------------------------------------------
__global__ __launch_bounds__(256, 2)
void k_conv3(const float* __restrict__ x, const float* __restrict__ w3,
             const float* __restrict__ b3, float* __restrict__ out)
{
    __shared__ uint32_t As[128][20];
    __shared__ uint32_t Bs[16][136];

    const int tid  = threadIdx.x;
    const int lane = tid & 31;
    const int wid  = tid >> 5;
    const int wm   = (wid >> 2) * 64;
    const int wn   = (wid & 3) * 32;
    const int rowBase = blockIdx.x * 128;
    const int nBase   = blockIdx.y * 128;

    const int arow = tid >> 2;
    const int akc  = (tid & 3) * 4;
    const int bk   = tid >> 5;
    const int bn0  = (tid & 31) * 4;

    const int lg = lane >> 2;
    const int lt = lane & 3;

    float c[4][4][4];
    #pragma unroll
    for (int i = 0; i < 4; i++)
        #pragma unroll
        for (int j = 0; j < 4; j++)
            #pragma unroll
            for (int t = 0; t < 4; t++) c[i][j][t] = 0.f;

    for (int kt = 0; kt < 128; kt += 16) {
        #pragma unroll
        for (int h = 0; h < 2; h++) {
            int r = arow + h * 64;
            float4 v = *(const float4*)(g_h2 + (size_t)(rowBase + r) * 128 + kt + akc);
            uint4 s = { f2tf(v.x), f2tf(v.y), f2tf(v.z), f2tf(v.w) };
            *(uint4*)&As[r][akc] = s;
        }
        #pragma unroll
        for (int h = 0; h < 2; h++) {
            int k = bk + h * 8;
            float4 v = *(const float4*)(w3 + (size_t)(kt + k) * 256 + nBase + bn0);
            uint4 s = { f2tf(v.x), f2tf(v.y), f2tf(v.z), f2tf(v.w) };
            *(uint4*)&Bs[k][bn0] = s;
        }
        __syncthreads();

        #pragma unroll
        for (int ks = 0; ks < 16; ks += 8) {
            uint32_t a[4][4];
            #pragma unroll
            for (int mi = 0; mi < 4; mi++) {
                int r0 = wm + mi * 16 + lg;
                a[mi][0] = As[r0    ][ks + lt    ];
                a[mi][1] = As[r0 + 8][ks + lt    ];
                a[mi][2] = As[r0    ][ks + lt + 4];
                a[mi][3] = As[r0 + 8][ks + lt + 4];
            }
            uint32_t b[4][2];
            #pragma unroll
            for (int nj = 0; nj < 4; nj++) {
                int nn = wn + nj * 8 + lg;
                b[nj][0] = Bs[ks + lt    ][nn];
                b[nj][1] = Bs[ks + lt + 4][nn];
            }
            #pragma unroll
            for (int mi = 0; mi < 4; mi++)
                #pragma unroll
                for (int nj = 0; nj < 4; nj++)
                    mma_tf32(c[mi][nj], a[mi], b[nj]);
        }
        __syncthreads();
    }

    float bv[4][2];
    #pragma unroll
    for (int nj = 0; nj < 4; nj++)
        #pragma unroll
        for (int t = 0; t < 2; t++)
            bv[nj][t] = b3[nBase + wn + nj * 8 + 2 * lt + t];

    #pragma unroll
    for (int mi = 0; mi < 4; mi++)
        #pragma unroll
        for (int h = 0; h < 2; h++) {
            size_t row = (size_t)(rowBase + wm + mi * 16 + lg + h * 8) * 256;
            #pragma unroll
            for (int nj = 0; nj < 4; nj++) {
                size_t off = row + nBase + wn + nj * 8 + 2 * lt;
                float2 xr = *(const float2*)(x + off);
                float2 o;
                o.x = fmaxf(c[mi][nj][2*h+0] + bv[nj][0] + xr.x, 0.f);
                o.y = fmaxf(c[mi][nj][2*h+1] + bv[nj][1] + xr.y, 0.f);
                *(float2*)(out + off) = o;
            }
        }
}

// ---------------------------------------------------------------------------
extern "C" void kernel_launch(void* const* d_in, const int* in_sizes, int n_in,
                              void* d_out, int out_size)
{
    const float* x   = (const float*)d_in[0];
    const float* w1  = (const float*)d_in[1];
    const float* b1  = (const float*)d_in[2];
    const float* g1  = (const float*)d_in[3];
    const float* be1 = (const float*)d_in[4];
    const float* m1  = (const float*)d_in[5];
    const float* v1  = (const float*)d_in[6];
    const float* w2  = (const float*)d_in[7];
    const float* b2  = (const float*)d_in[8];
    const float* g2  = (const float*)d_in[9];
    const float* be2 = (const float*)d_in[10];
    const float* m2  = (const float*)d_in[11];
    const float* v2  = (const float*)d_in[12];
    const float* w3  = (const float*)d_in[13];
    const float* b3  = (const float*)d_in[14];
    float* out = (float*)d_out;

    k_conv1<<<Mn/128, 256>>>(x, w1, b1, g1, be1, m1, v1);
    k_conv2<<<dim3(56, 32, 4), 256>>>(w2, b2, g2, be2, m2, v2);
    k_conv3<<<dim3(Mn/128, 2), 256>>>(x, w3, b3, out);
}